// round 1
// baseline (speedup 1.0000x reference)
#include <cuda_runtime.h>
#include <math.h>

#define Bb 2048
#define Nn 512
#define Hh 20
#define Tt 3

typedef unsigned long long u64;

// Scratch (static __device__ arrays: allowed, no runtime allocation)
__device__ float g_AT[Nn * Nn];                       // AT[m][n] = A_in[n][m]
__device__ float g_nodes[(size_t)Bb * Nn * Hh];       // node state between steps

// ---------------- packed f32x2 helpers (Blackwell) ----------------
__device__ __forceinline__ u64 pack2(float lo, float hi) {
    u64 r; asm("mov.b64 %0, {%1, %2};" : "=l"(r) : "f"(lo), "f"(hi)); return r;
}
__device__ __forceinline__ void unpack2(u64 v, float& lo, float& hi) {
    asm("mov.b64 {%0, %1}, %2;" : "=f"(lo), "=f"(hi) : "l"(v));
}
__device__ __forceinline__ u64 fma2(u64 a, u64 b, u64 c) {
    u64 d; asm("fma.rn.f32x2 %0, %1, %2, %3;" : "=l"(d) : "l"(a), "l"(b), "l"(c)); return d;
}

// ---------------- A transpose (cheap, once per launch) ----------------
__global__ void transpose_kernel(const float* __restrict__ A, float* __restrict__ AT) {
    __shared__ float tile[32][33];
    int x = blockIdx.x * 32 + threadIdx.x;
    int y = blockIdx.y * 32 + threadIdx.y;
    #pragma unroll
    for (int i = 0; i < 32; i += 8)
        tile[threadIdx.y + i][threadIdx.x] = A[(y + i) * Nn + x];
    __syncthreads();
    int xo = blockIdx.y * 32 + threadIdx.x;
    int yo = blockIdx.x * 32 + threadIdx.y;
    #pragma unroll
    for (int i = 0; i < 32; i += 8)
        AT[(yo + i) * Nn + xo] = tile[threadIdx.x][threadIdx.y + i];
}

// ---------------- smem layout (floats) ----------------
#define S_X    0            // 512*20 = 10240
#define S_W3W  10240        // 800
#define S_W3U  11040        // 400
#define S_W4W  11440        // 800
#define S_W4U  12240        // 400
#define S_W5W  12640        // 800
#define S_W5U  13440        // 400
#define S_WOUT 13840        // 800
#define S_BOUT 14640        // 20
#define S_TOTAL 14660

__device__ __forceinline__ float sigmoidf_(float v) {
    return 1.f / (1.f + expf(-v));
}

// One block per batch element b; thread n handles node n (all H features).
// Fused: aggregation (A@X, A^T@X) + GRU gates + state update + step output.
__global__ void __launch_bounds__(Nn, 1) step_kernel(
    const float* __restrict__ nodes_in,   // [B,N,H] current state (x on t=0)
    const float* __restrict__ x,          // [B,N,H] original input (skip-cat)
    const float* __restrict__ A,          // [N,N]
    const float* __restrict__ W3w, const float* __restrict__ W3u,
    const float* __restrict__ W4w, const float* __restrict__ W4u,
    const float* __restrict__ W5w, const float* __restrict__ W5u,
    const float* __restrict__ Wout, const float* __restrict__ bout,
    float* __restrict__ out_t)            // [B,N,H] slice of output for this step
{
    extern __shared__ float sm[];
    const int n = threadIdx.x;
    const int b = blockIdx.x;

    // Stage this batch's node tile into smem (coalesced)
    const float* nb = nodes_in + (size_t)b * Nn * Hh;
    for (int i = n; i < Nn * Hh; i += Nn) sm[S_X + i] = nb[i];
    // Stage gate weights
    for (int i = n; i < 2 * Hh * Hh; i += Nn) {
        sm[S_W3W + i] = W3w[i];
        sm[S_W4W + i] = W4w[i];
        sm[S_W5W + i] = W5w[i];
        sm[S_WOUT + i] = Wout[i];
    }
    for (int i = n; i < Hh * Hh; i += Nn) {
        sm[S_W3U + i] = W3u[i];
        sm[S_W4U + i] = W4u[i];
        sm[S_W5U + i] = W5u[i];
    }
    if (n < Hh) sm[S_BOUT + n] = bout[n];
    __syncthreads();

    // ---------------- aggregation: agg_in[n,:] = sum_m A[n][m] x[m,:]
    //                  agg_out[n,:] = sum_m A[m][n] x[m,:]
    // packed f32x2 accumulators (10 pairs each = 20 floats each)
    u64 accin[10], accout[10];
    const u64 z64 = pack2(0.f, 0.f);
    #pragma unroll
    for (int j = 0; j < 10; j++) { accin[j] = z64; accout[j] = z64; }

    const float* Acol  = A + n;      // A[m*Nn + n]  -> coalesced over n
    const float* ATcol = g_AT + n;   // AT[m*Nn + n] = A[n][m] -> coalesced over n

    #pragma unroll 2
    for (int m = 0; m < Nn; m++) {
        float a_i = ATcol[m * Nn];
        float a_o = Acol[m * Nn];
        u64 ai = pack2(a_i, a_i);
        u64 ao = pack2(a_o, a_o);
        const u64* xr = (const u64*)(sm + S_X + m * Hh);  // 80B rows, 8B aligned
        #pragma unroll
        for (int j = 0; j < 10; j++) {
            u64 xv = xr[j];
            accin[j]  = fma2(ai, xv, accin[j]);
            accout[j] = fma2(ao, xv, accout[j]);
        }
    }

    float ain[Hh], aout[Hh], fn[Hh];
    #pragma unroll
    for (int j = 0; j < 10; j++) {
        unpack2(accin[j],  ain[2 * j],  ain[2 * j + 1]);
        unpack2(accout[j], aout[2 * j], aout[2 * j + 1]);
    }
    {
        const float* myx = sm + S_X + n * Hh;
        #pragma unroll
        for (int j = 0; j < Hh; j++) fn[j] = myx[j];
    }

    // ---------------- r gate, then rf = sigmoid(r) * fn
    float rf[Hh];
    #pragma unroll
    for (int h = 0; h < Hh; h++) {
        const float* w  = sm + S_W4W + h * 2 * Hh;
        const float* wu = sm + S_W4U + h * Hh;
        float s = 0.f;
        #pragma unroll
        for (int j = 0; j < Hh; j++) s = fmaf(ain[j],  w[j],      s);
        #pragma unroll
        for (int j = 0; j < Hh; j++) s = fmaf(aout[j], w[Hh + j], s);
        #pragma unroll
        for (int j = 0; j < Hh; j++) s = fmaf(fn[j],   wu[j],     s);
        rf[h] = s;
    }
    #pragma unroll
    for (int h = 0; h < Hh; h++) rf[h] = fn[h] * sigmoidf_(rf[h]);

    // ---------------- z gate + candidate + state update
    float fnew[Hh];
    #pragma unroll
    for (int h = 0; h < Hh; h++) {
        const float* wz  = sm + S_W3W + h * 2 * Hh;
        const float* wzu = sm + S_W3U + h * Hh;
        const float* wh  = sm + S_W5W + h * 2 * Hh;
        const float* whu = sm + S_W5U + h * Hh;
        float sz = 0.f, sh = 0.f;
        #pragma unroll
        for (int j = 0; j < Hh; j++) { sz = fmaf(ain[j],  wz[j],      sz); sh = fmaf(ain[j],  wh[j],      sh); }
        #pragma unroll
        for (int j = 0; j < Hh; j++) { sz = fmaf(aout[j], wz[Hh + j], sz); sh = fmaf(aout[j], wh[Hh + j], sh); }
        #pragma unroll
        for (int j = 0; j < Hh; j++) { sz = fmaf(fn[j],   wzu[j],     sz); sh = fmaf(rf[j],   whu[j],     sh); }
        float zv = sigmoidf_(sz);
        float hv = tanhf(sh);
        fnew[h] = (1.f - zv) * fn[h] + zv * hv;
    }

    // ---------------- step output: out = [fnew, x_orig] @ Wout^T + b
    float xo[Hh];
    {
        const float* xr = x + (size_t)b * Nn * Hh + (size_t)n * Hh;  // 80B row, 16B aligned
        #pragma unroll
        for (int j = 0; j < 5; j++) {
            float4 v = ((const float4*)xr)[j];
            xo[4 * j + 0] = v.x; xo[4 * j + 1] = v.y;
            xo[4 * j + 2] = v.z; xo[4 * j + 3] = v.w;
        }
    }
    float o[Hh];
    #pragma unroll
    for (int h = 0; h < Hh; h++) {
        const float* w = sm + S_WOUT + h * 2 * Hh;
        float s = sm[S_BOUT + h];
        #pragma unroll
        for (int j = 0; j < Hh; j++) s = fmaf(fnew[j], w[j],      s);
        #pragma unroll
        for (int j = 0; j < Hh; j++) s = fmaf(xo[j],   w[Hh + j], s);
        o[h] = s;
    }

    // ---------------- vectorized writes: output slice + next node state
    {
        float* op = out_t   + (size_t)b * Nn * Hh + (size_t)n * Hh;
        float* np = g_nodes + (size_t)b * Nn * Hh + (size_t)n * Hh;
        #pragma unroll
        for (int j = 0; j < 5; j++) {
            ((float4*)op)[j] = make_float4(o[4 * j], o[4 * j + 1], o[4 * j + 2], o[4 * j + 3]);
            ((float4*)np)[j] = make_float4(fnew[4 * j], fnew[4 * j + 1], fnew[4 * j + 2], fnew[4 * j + 3]);
        }
    }
}

extern "C" void kernel_launch(void* const* d_in, const int* in_sizes, int n_in,
                              void* d_out, int out_size) {
    (void)in_sizes; (void)n_in; (void)out_size;
    const float* x    = (const float*)d_in[0];
    const float* A    = (const float*)d_in[1];
    const float* W3w  = (const float*)d_in[2];
    const float* W3u  = (const float*)d_in[3];
    const float* W4w  = (const float*)d_in[4];
    const float* W4u  = (const float*)d_in[5];
    const float* W5w  = (const float*)d_in[6];
    const float* W5u  = (const float*)d_in[7];
    const float* Wout = (const float*)d_in[8];
    const float* bo   = (const float*)d_in[9];
    float* out = (float*)d_out;

    float* AT = nullptr;
    float* nodes = nullptr;
    cudaGetSymbolAddress((void**)&AT, g_AT);
    cudaGetSymbolAddress((void**)&nodes, g_nodes);

    const size_t smem_bytes = (size_t)S_TOTAL * sizeof(float);
    cudaFuncSetAttribute(step_kernel, cudaFuncAttributeMaxDynamicSharedMemorySize,
                         (int)smem_bytes);

    transpose_kernel<<<dim3(16, 16), dim3(32, 8)>>>(A, AT);

    const size_t slab = (size_t)Bb * Nn * Hh;
    for (int t = 0; t < Tt; t++) {
        const float* nin = (t == 0) ? x : nodes;
        step_kernel<<<Bb, Nn, smem_bytes>>>(nin, x, A,
                                            W3w, W3u, W4w, W4u, W5w, W5u,
                                            Wout, bo, out + (size_t)t * slab);
    }
}

// round 3
// speedup vs baseline: 2.1440x; 2.1440x over previous
#include <cuda_runtime.h>
#include <cuda_fp16.h>
#include <cstdint>

#define Bb 2048
#define Nn 512
#define Hh 20
#define Tt 3
#define BH (Bb * Hh)          // 40960 columns

typedef unsigned long long u64;
typedef unsigned int u32;

// ---------------- device scratch ----------------
__device__ __half g_Ah[Nn * Nn];            // A   fp16, [row][k]
__device__ __half g_ATh[Nn * Nn];           // A^T fp16
__device__ __half g_Sh[(size_t)BH * Nn];    // state fp16, [col][node]  (K-major)
__device__ float  g_Sf[(size_t)BH * Nn];    // state fp32, [col][node]
__device__ float  g_agg1[(size_t)Nn * BH];  // A  @X  [node][col]
__device__ float  g_agg2[(size_t)Nn * BH];  // A^T@X  [node][col]

// ---------------- helpers ----------------
__device__ __forceinline__ u32 smem_u32(const void* p) {
    u32 a; asm("{ .reg .u64 t; cvta.to.shared.u64 t, %1; cvt.u32.u64 %0, t; }"
               : "=r"(a) : "l"(p)); return a;
}
__device__ __forceinline__ u64 pack2(float lo, float hi) {
    u64 r; asm("mov.b64 %0, {%1, %2};" : "=l"(r) : "f"(lo), "f"(hi)); return r;
}
__device__ __forceinline__ void unpack2(u64 v, float& lo, float& hi) {
    asm("mov.b64 {%0, %1}, %2;" : "=f"(lo), "=f"(hi) : "l"(v));
}
__device__ __forceinline__ u64 fma2(u64 a, u64 b, u64 c) {
    u64 d; asm("fma.rn.f32x2 %0, %1, %2, %3;" : "=l"(d) : "l"(a), "l"(b), "l"(c)); return d;
}
__device__ __forceinline__ float fsum2(u64 v) { float a, b; unpack2(v, a, b); return a + b; }

__device__ __forceinline__ float fast_sigmoid(float v) {
    return __fdividef(1.f, 1.f + __expf(-v));
}
__device__ __forceinline__ float fast_tanh(float v) {
    return 1.f - __fdividef(2.f, __expf(2.f * v) + 1.f);
}

__device__ __forceinline__ void cp16(u32 dst, const void* src) {
    asm volatile("cp.async.cg.shared.global [%0], [%1], 16;" :: "r"(dst), "l"(src) : "memory");
}
#define CP_COMMIT() asm volatile("cp.async.commit_group;" ::: "memory")
#define CP_WAIT1()  asm volatile("cp.async.wait_group 1;" ::: "memory")

__device__ __forceinline__ void ldsm4(u32& r0, u32& r1, u32& r2, u32& r3, u32 addr) {
    asm volatile("ldmatrix.sync.aligned.m8n8.x4.shared.b16 {%0,%1,%2,%3}, [%4];"
                 : "=r"(r0), "=r"(r1), "=r"(r2), "=r"(r3) : "r"(addr));
}
__device__ __forceinline__ void mma16816(float& c0, float& c1, float& c2, float& c3,
                                         u32 a0, u32 a1, u32 a2, u32 a3, u32 b0, u32 b1) {
    asm volatile("mma.sync.aligned.m16n8k16.row.col.f32.f16.f16.f32 "
                 "{%0,%1,%2,%3}, {%4,%5,%6,%7}, {%8,%9}, {%0,%1,%2,%3};"
                 : "+f"(c0), "+f"(c1), "+f"(c2), "+f"(c3)
                 : "r"(a0), "r"(a1), "r"(a2), "r"(a3), "r"(b0), "r"(b1));
}

// ---------------- prep: A -> fp16 A, A^T ----------------
__global__ void conv_A_kernel(const float* __restrict__ A) {
    __shared__ float t[32][33];
    int x = blockIdx.x * 32 + threadIdx.x;
    int y = blockIdx.y * 32 + threadIdx.y;
    float v = A[y * Nn + x];
    g_Ah[y * Nn + x] = __float2half(v);
    t[threadIdx.y][threadIdx.x] = v;
    __syncthreads();
    int xo = blockIdx.y * 32 + threadIdx.x;
    int yo = blockIdx.x * 32 + threadIdx.y;
    g_ATh[yo * Nn + xo] = __float2half(t[threadIdx.x][threadIdx.y]);
}

// ---------------- prep: x [B,N,H] -> state [BH][N] (fp32 + fp16) ----------------
__global__ void conv_X_kernel(const float* __restrict__ x) {
    int b = blockIdx.x, n = threadIdx.x;
    const float4* xp = (const float4*)(x + ((size_t)b * Nn + n) * Hh);
    float v[Hh];
    #pragma unroll
    for (int j = 0; j < 5; j++) {
        float4 q = xp[j];
        v[4 * j] = q.x; v[4 * j + 1] = q.y; v[4 * j + 2] = q.z; v[4 * j + 3] = q.w;
    }
    #pragma unroll
    for (int h = 0; h < Hh; h++) {
        size_t o = (size_t)(b * Hh + h) * Nn + n;
        g_Sf[o] = v[h];
        g_Sh[o] = __float2half(v[h]);
    }
}

// ---------------- HMMA GEMM: agg1 = A@X, agg2 = A^T@X ----------------
// CTA: 128 m-nodes x 128 n-cols, K in chunks of 64, double-buffered cp.async.
// smem stage layout: A [128][64] @ +0, AT @ +16384, X [128 cols][64 k] @ +32768.
#define STAGE_B 49152

__global__ void __launch_bounds__(512, 1) gemm_kernel() {
    extern __shared__ char smraw[];
    const u32 smem = (smem_u32(smraw) + 127) & ~127u;
    const int tid = threadIdx.x;
    const int wid = tid >> 5;
    const int lane = tid & 31;
    const int ntile = blockIdx.x;    // 0..319
    const int mtile = blockIdx.y;    // 0..3

    // warp mapping: half 0 -> agg1 (A), half 1 -> agg2 (AT)
    const int half = wid >> 3;
    const int wl = wid & 7;
    const int m_off = (wl & 1) * 64;
    const int n_off = (wl >> 1) * 32;

    auto load_stage = [&](int kc, int s) {
        const u32 base = smem + s * STAGE_B;
        #pragma unroll
        for (int i = 0; i < 6; i++) {
            int idx = tid + i * 512;       // 0..3071
            int t = idx >> 10;             // 0=A, 1=AT, 2=X
            int r = (idx >> 3) & 127;
            int c = idx & 7;
            u32 dst = base + t * 16384 + r * 128 + (u32)((c ^ (r & 7)) << 4);
            const __half* src;
            if (t == 0)      src = g_Ah  + (size_t)(mtile * 128 + r) * Nn + kc * 64 + c * 8;
            else if (t == 1) src = g_ATh + (size_t)(mtile * 128 + r) * Nn + kc * 64 + c * 8;
            else             src = g_Sh  + (size_t)(ntile * 128 + r) * Nn + kc * 64 + c * 8;
            cp16(dst, src);
        }
        CP_COMMIT();
    };

    float c[4][4][4];
    #pragma unroll
    for (int mt = 0; mt < 4; mt++)
        #pragma unroll
        for (int nt = 0; nt < 4; nt++)
            #pragma unroll
            for (int q = 0; q < 4; q++) c[mt][nt][q] = 0.f;

    // per-lane ldmatrix row/col constants
    const int rA = m_off + (lane & 15);
    const int cA = lane >> 4;
    const int sA = rA & 7;
    const int rB = n_off + ((lane >> 4) & 1) * 8 + (lane & 7);
    const int cB = (lane >> 3) & 1;
    const int sB = rB & 7;

    load_stage(0, 0);
    load_stage(1, 1);

    for (int kc = 0; kc < 8; kc++) {
        const int s = kc & 1;
        CP_WAIT1();
        __syncthreads();

        const u32 Abase = smem + s * STAGE_B + half * 16384 + (u32)rA * 128;
        const u32 Xbase = smem + s * STAGE_B + 32768 + (u32)rB * 128;

        #pragma unroll
        for (int ks = 0; ks < 4; ks++) {
            u32 a[4][4], b[2][4];
            #pragma unroll
            for (int mt = 0; mt < 4; mt++) {
                u32 addr = Abase + mt * 2048 + (u32)(((ks * 2 + cA) ^ sA) << 4);
                ldsm4(a[mt][0], a[mt][1], a[mt][2], a[mt][3], addr);
            }
            #pragma unroll
            for (int nt2 = 0; nt2 < 2; nt2++) {
                u32 addr = Xbase + nt2 * 2048 + (u32)(((ks * 2 + cB) ^ sB) << 4);
                ldsm4(b[nt2][0], b[nt2][1], b[nt2][2], b[nt2][3], addr);
            }
            #pragma unroll
            for (int mt = 0; mt < 4; mt++)
                #pragma unroll
                for (int nt = 0; nt < 4; nt++) {
                    u32 b0 = b[nt >> 1][(nt & 1) * 2];
                    u32 b1 = b[nt >> 1][(nt & 1) * 2 + 1];
                    mma16816(c[mt][nt][0], c[mt][nt][1], c[mt][nt][2], c[mt][nt][3],
                             a[mt][0], a[mt][1], a[mt][2], a[mt][3], b0, b1);
                }
        }
        __syncthreads();
        if (kc + 2 < 8) load_stage(kc + 2, s);
    }

    // epilogue: direct global stores
    float* C = half ? g_agg2 : g_agg1;
    #pragma unroll
    for (int mt = 0; mt < 4; mt++) {
        int m = mtile * 128 + m_off + mt * 16 + (lane >> 2);
        #pragma unroll
        for (int nt = 0; nt < 4; nt++) {
            int col = ntile * 128 + n_off + nt * 8 + (lane & 3) * 2;
            float2* p0 = (float2*)(C + (size_t)m * BH + col);
            float2* p1 = (float2*)(C + (size_t)(m + 8) * BH + col);
            *p0 = make_float2(c[mt][nt][0], c[mt][nt][1]);
            *p1 = make_float2(c[mt][nt][2], c[mt][nt][3]);
        }
    }
}

// ---------------- gates: GRU update + step output ----------------
__global__ void __launch_bounds__(256) gates_kernel(
    const float* __restrict__ x,
    const float* __restrict__ W3w, const float* __restrict__ W3u,
    const float* __restrict__ W4w, const float* __restrict__ W4u,
    const float* __restrict__ W5w, const float* __restrict__ W5u,
    const float* __restrict__ Wout, const float* __restrict__ bout,
    float* __restrict__ out_t)
{
    __shared__ float sWz[Hh][60], sWr[Hh][60], sWh[Hh][60];
    __shared__ float sWo[Hh][40], sB[Hh];
    const int tid = threadIdx.x;
    for (int i = tid; i < Hh * 2 * Hh; i += 256) {
        int h = i / 40, j = i % 40;
        sWz[h][j] = W3w[i]; sWr[h][j] = W4w[i]; sWh[h][j] = W5w[i];
        sWo[h][j] = Wout[i];
    }
    for (int i = tid; i < Hh * Hh; i += 256) {
        int h = i / Hh, j = i % Hh;
        sWz[h][40 + j] = W3u[i]; sWr[h][40 + j] = W4u[i]; sWh[h][40 + j] = W5u[i];
    }
    if (tid < Hh) sB[tid] = bout[tid];
    __syncthreads();

    const int b = blockIdx.x;
    const int n = blockIdx.y * 256 + tid;

    // data vector: packed pairs of [agg_in(20), agg_out(20), fn(20)]
    u64 d2[30];
    float fn[Hh];
    {
        const float4* a1 = (const float4*)(g_agg1 + (size_t)n * BH + b * Hh);
        const float4* a2 = (const float4*)(g_agg2 + (size_t)n * BH + b * Hh);
        #pragma unroll
        for (int j = 0; j < 5; j++) {
            float4 q = a1[j];
            d2[2 * j]     = pack2(q.x, q.y);
            d2[2 * j + 1] = pack2(q.z, q.w);
        }
        #pragma unroll
        for (int j = 0; j < 5; j++) {
            float4 q = a2[j];
            d2[10 + 2 * j]     = pack2(q.x, q.y);
            d2[10 + 2 * j + 1] = pack2(q.z, q.w);
        }
        #pragma unroll
        for (int h = 0; h < Hh; h++)
            fn[h] = g_Sf[(size_t)(b * Hh + h) * Nn + n];
        #pragma unroll
        for (int j = 0; j < 10; j++)
            d2[20 + j] = pack2(fn[2 * j], fn[2 * j + 1]);
    }

    // z and r gates
    float zv[Hh];
    {
        float rv[Hh];
        #pragma unroll
        for (int h = 0; h < Hh; h++) {
            u64 az = pack2(0.f, 0.f), ar = az;
            const float4* wz = (const float4*)&sWz[h][0];
            const float4* wr = (const float4*)&sWr[h][0];
            #pragma unroll
            for (int q = 0; q < 15; q++) {
                float4 a = wz[q], cc = wr[q];
                az = fma2(pack2(a.x, a.y), d2[2 * q], az);
                az = fma2(pack2(a.z, a.w), d2[2 * q + 1], az);
                ar = fma2(pack2(cc.x, cc.y), d2[2 * q], ar);
                ar = fma2(pack2(cc.z, cc.w), d2[2 * q + 1], ar);
            }
            zv[h] = fast_sigmoid(fsum2(az));
            rv[h] = fast_sigmoid(fsum2(ar));
        }
        #pragma unroll
        for (int j = 0; j < 10; j++)
            d2[20 + j] = pack2(rv[2 * j] * fn[2 * j], rv[2 * j + 1] * fn[2 * j + 1]);
    }

    // candidate + state update
    float fnew[Hh];
    #pragma unroll
    for (int h = 0; h < Hh; h++) {
        u64 ah = pack2(0.f, 0.f);
        const float4* wh = (const float4*)&sWh[h][0];
        #pragma unroll
        for (int q = 0; q < 15; q++) {
            float4 a = wh[q];
            ah = fma2(pack2(a.x, a.y), d2[2 * q], ah);
            ah = fma2(pack2(a.z, a.w), d2[2 * q + 1], ah);
        }
        float hv = fast_tanh(fsum2(ah));
        fnew[h] = (1.f - zv[h]) * fn[h] + zv[h] * hv;
    }

    // write back state (fp32 + fp16)
    #pragma unroll
    for (int h = 0; h < Hh; h++) {
        size_t o = (size_t)(b * Hh + h) * Nn + n;
        g_Sf[o] = fnew[h];
        g_Sh[o] = __float2half(fnew[h]);
    }

    // step output: [fnew, x] @ Wout^T + b
    u64 e2[20];
    #pragma unroll
    for (int j = 0; j < 10; j++) e2[j] = pack2(fnew[2 * j], fnew[2 * j + 1]);
    {
        const float4* xp = (const float4*)(x + ((size_t)b * Nn + n) * Hh);
        #pragma unroll
        for (int j = 0; j < 5; j++) {
            float4 q = xp[j];
            e2[10 + 2 * j]     = pack2(q.x, q.y);
            e2[10 + 2 * j + 1] = pack2(q.z, q.w);
        }
    }
    float o[Hh];
    #pragma unroll
    for (int h = 0; h < Hh; h++) {
        u64 acc = pack2(sB[h], 0.f);
        const float4* w = (const float4*)&sWo[h][0];
        #pragma unroll
        for (int q = 0; q < 10; q++) {
            float4 a = w[q];
            acc = fma2(pack2(a.x, a.y), e2[2 * q], acc);
            acc = fma2(pack2(a.z, a.w), e2[2 * q + 1], acc);
        }
        o[h] = fsum2(acc);
    }
    float4* op = (float4*)(out_t + ((size_t)b * Nn + n) * Hh);
    #pragma unroll
    for (int j = 0; j < 5; j++)
        op[j] = make_float4(o[4 * j], o[4 * j + 1], o[4 * j + 2], o[4 * j + 3]);
}

// ---------------- host ----------------
extern "C" void kernel_launch(void* const* d_in, const int* in_sizes, int n_in,
                              void* d_out, int out_size) {
    (void)in_sizes; (void)n_in; (void)out_size;
    const float* x    = (const float*)d_in[0];
    const float* A    = (const float*)d_in[1];
    const float* W3w  = (const float*)d_in[2];
    const float* W3u  = (const float*)d_in[3];
    const float* W4w  = (const float*)d_in[4];
    const float* W4u  = (const float*)d_in[5];
    const float* W5w  = (const float*)d_in[6];
    const float* W5u  = (const float*)d_in[7];
    const float* Wout = (const float*)d_in[8];
    const float* bo   = (const float*)d_in[9];
    float* out = (float*)d_out;

    const int gemm_smem = 2 * STAGE_B + 128;
    cudaFuncSetAttribute(gemm_kernel, cudaFuncAttributeMaxDynamicSharedMemorySize, gemm_smem);

    conv_A_kernel<<<dim3(16, 16), dim3(32, 32)>>>(A);
    conv_X_kernel<<<Bb, Nn>>>(x);

    const size_t slab = (size_t)Bb * Nn * Hh;
    for (int t = 0; t < Tt; t++) {
        gemm_kernel<<<dim3(BH / 128, Nn / 128), 512, gemm_smem>>>();
        gates_kernel<<<dim3(Bb, 2), 256>>>(x, W3w, W3u, W4w, W4u, W5w, W5u,
                                           Wout, bo, out + (size_t)t * slab);
    }
}

// round 5
// speedup vs baseline: 2.7055x; 1.2619x over previous
#include <cuda_runtime.h>
#include <cuda_fp16.h>
#include <cstdint>

#define Bb 2048
#define Nn 512
#define Hh 20
#define Tt 3
#define BH (Bb * Hh)          // 40960 columns

typedef unsigned long long u64;
typedef unsigned int u32;

// ---------------- device scratch ----------------
__device__ __half g_Ah[Nn * Nn];            // A   fp16, [row][k]
__device__ __half g_ATh[Nn * Nn];           // A^T fp16
__device__ __half g_Sh[(size_t)BH * Nn];    // state fp16, [col][node]  (K-major)
__device__ float  g_Sf[(size_t)BH * Nn];    // state fp32, [col][node]
__device__ float  g_Xtf[(size_t)BH * Nn];   // x fp32, [col][node] (transposed copy)
__device__ float  g_agg1[(size_t)BH * Nn];  // A  @X  TRANSPOSED: [col][node]
__device__ float  g_agg2[(size_t)BH * Nn];  // A^T@X  TRANSPOSED: [col][node]

// ---------------- helpers ----------------
__device__ __forceinline__ u32 smem_u32(const void* p) {
    u32 a; asm("{ .reg .u64 t; cvta.to.shared.u64 t, %1; cvt.u32.u64 %0, t; }"
               : "=r"(a) : "l"(p)); return a;
}
__device__ __forceinline__ u64 pack2(float lo, float hi) {
    u64 r; asm("mov.b64 %0, {%1, %2};" : "=l"(r) : "f"(lo), "f"(hi)); return r;
}
__device__ __forceinline__ void unpack2(u64 v, float& lo, float& hi) {
    asm("mov.b64 {%0, %1}, %2;" : "=f"(lo), "=f"(hi) : "l"(v));
}
__device__ __forceinline__ u64 fma2(u64 a, u64 b, u64 c) {
    u64 d; asm("fma.rn.f32x2 %0, %1, %2, %3;" : "=l"(d) : "l"(a), "l"(b), "l"(c)); return d;
}
__device__ __forceinline__ float fsum2(u64 v) { float a, b; unpack2(v, a, b); return a + b; }

__device__ __forceinline__ float tanh_fast(float x) {
    float y; asm("tanh.approx.f32 %0, %1;" : "=f"(y) : "f"(x)); return y;
}
__device__ __forceinline__ float sigmoid_fast(float x) {
    return fmaf(tanh_fast(0.5f * x), 0.5f, 0.5f);
}

__device__ __forceinline__ void cp16(u32 dst, const void* src) {
    asm volatile("cp.async.cg.shared.global [%0], [%1], 16;" :: "r"(dst), "l"(src) : "memory");
}
#define CP_COMMIT() asm volatile("cp.async.commit_group;" ::: "memory")
#define CP_WAIT1()  asm volatile("cp.async.wait_group 1;" ::: "memory")
#define CP_WAIT0()  asm volatile("cp.async.wait_group 0;" ::: "memory")

__device__ __forceinline__ void ldsm4(u32& r0, u32& r1, u32& r2, u32& r3, u32 addr) {
    asm volatile("ldmatrix.sync.aligned.m8n8.x4.shared.b16 {%0,%1,%2,%3}, [%4];"
                 : "=r"(r0), "=r"(r1), "=r"(r2), "=r"(r3) : "r"(addr));
}
__device__ __forceinline__ void mma16816(float& c0, float& c1, float& c2, float& c3,
                                         u32 a0, u32 a1, u32 a2, u32 a3, u32 b0, u32 b1) {
    asm volatile("mma.sync.aligned.m16n8k16.row.col.f32.f16.f16.f32 "
                 "{%0,%1,%2,%3}, {%4,%5,%6,%7}, {%8,%9}, {%0,%1,%2,%3};"
                 : "+f"(c0), "+f"(c1), "+f"(c2), "+f"(c3)
                 : "r"(a0), "r"(a1), "r"(a2), "r"(a3), "r"(b0), "r"(b1));
}

// ---------------- prep: A -> fp16 A, A^T ----------------
__global__ void conv_A_kernel(const float* __restrict__ A) {
    __shared__ float t[32][33];
    int x = blockIdx.x * 32 + threadIdx.x;
    int y = blockIdx.y * 32 + threadIdx.y;
    float v = A[y * Nn + x];
    g_Ah[y * Nn + x] = __float2half(v);
    t[threadIdx.y][threadIdx.x] = v;
    __syncthreads();
    int xo = blockIdx.y * 32 + threadIdx.x;
    int yo = blockIdx.x * 32 + threadIdx.y;
    g_ATh[yo * Nn + xo] = __float2half(t[threadIdx.x][threadIdx.y]);
}

// ---------------- prep: x [B,N,H] -> [col][node] fp32/fp16 ----------------
__global__ void conv_X_kernel(const float* __restrict__ x) {
    int b = blockIdx.x, n = threadIdx.x;
    const float4* xp = (const float4*)(x + ((size_t)b * Nn + n) * Hh);
    float v[Hh];
    #pragma unroll
    for (int j = 0; j < 5; j++) {
        float4 q = xp[j];
        v[4 * j] = q.x; v[4 * j + 1] = q.y; v[4 * j + 2] = q.z; v[4 * j + 3] = q.w;
    }
    #pragma unroll
    for (int h = 0; h < Hh; h++) {
        size_t o = (size_t)(b * Hh + h) * Nn + n;
        g_Sf[o] = v[h];
        g_Xtf[o] = v[h];
        g_Sh[o] = __float2half(v[h]);
    }
}

// ---------------- HMMA GEMM: agg1 = A@X, agg2 = A^T@X (transposed output) ---
// CTA: 128 m-nodes x 128 n-cols, K chunks of 64, double-buffered cp.async.
// smem stage: A @ +0, AT @ +16384, X @ +32768 (each 128x64 fp16, XOR swizzle).
#define STAGE_B 49152
#define TRS 132   // transpose smem stride (floats)

__global__ void __launch_bounds__(512, 1) gemm_kernel() {
    extern __shared__ char smraw[];
    // generic aligned base (for normal C++ smem access) + matching shared-space u32
    char* smg = (char*)(((uintptr_t)smraw + 127) & ~(uintptr_t)127);
    const u32 smem = smem_u32(smg);
    const int tid = threadIdx.x;
    const int wid = tid >> 5;
    const int lane = tid & 31;
    const int ntile = blockIdx.x;    // 0..319
    const int mtile = blockIdx.y;    // 0..3

    const int half = wid >> 3;       // 0 -> agg1 (A), 1 -> agg2 (AT)
    const int wl = wid & 7;
    const int m_off = (wl & 1) * 64;
    const int n_off = (wl >> 1) * 32;

    auto load_stage = [&](int kc, int s) {
        const u32 base = smem + s * STAGE_B;
        #pragma unroll
        for (int i = 0; i < 6; i++) {
            int idx = tid + i * 512;       // 0..3071
            int t = idx >> 10;             // 0=A, 1=AT, 2=X
            int r = (idx >> 3) & 127;
            int c = idx & 7;
            u32 dst = base + t * 16384 + r * 128 + (u32)((c ^ (r & 7)) << 4);
            const __half* src;
            if (t == 0)      src = g_Ah  + (size_t)(mtile * 128 + r) * Nn + kc * 64 + c * 8;
            else if (t == 1) src = g_ATh + (size_t)(mtile * 128 + r) * Nn + kc * 64 + c * 8;
            else             src = g_Sh  + (size_t)(ntile * 128 + r) * Nn + kc * 64 + c * 8;
            cp16(dst, src);
        }
        CP_COMMIT();
    };

    float c[4][4][4];
    #pragma unroll
    for (int mt = 0; mt < 4; mt++)
        #pragma unroll
        for (int nt = 0; nt < 4; nt++)
            #pragma unroll
            for (int q = 0; q < 4; q++) c[mt][nt][q] = 0.f;

    const int rA = m_off + (lane & 15);
    const int cA = lane >> 4;
    const int sA = rA & 7;
    const int rB = n_off + ((lane >> 4) & 1) * 8 + (lane & 7);
    const int cB = (lane >> 3) & 1;
    const int sB = rB & 7;

    load_stage(0, 0);
    load_stage(1, 1);

    for (int kc = 0; kc < 8; kc++) {
        const int s = kc & 1;
        if (kc >= 6) CP_WAIT0(); else CP_WAIT1();
        __syncthreads();

        const u32 Abase = smem + s * STAGE_B + half * 16384 + (u32)rA * 128;
        const u32 Xbase = smem + s * STAGE_B + 32768 + (u32)rB * 128;

        #pragma unroll
        for (int ks = 0; ks < 4; ks++) {
            u32 a[4][4], b[2][4];
            #pragma unroll
            for (int mt = 0; mt < 4; mt++) {
                u32 addr = Abase + mt * 2048 + (u32)(((ks * 2 + cA) ^ sA) << 4);
                ldsm4(a[mt][0], a[mt][1], a[mt][2], a[mt][3], addr);
            }
            #pragma unroll
            for (int nt2 = 0; nt2 < 2; nt2++) {
                u32 addr = Xbase + nt2 * 2048 + (u32)(((ks * 2 + cB) ^ sB) << 4);
                ldsm4(b[nt2][0], b[nt2][1], b[nt2][2], b[nt2][3], addr);
            }
            #pragma unroll
            for (int mt = 0; mt < 4; mt++)
                #pragma unroll
                for (int nt = 0; nt < 4; nt++) {
                    u32 b0 = b[nt >> 1][(nt & 1) * 2];
                    u32 b1 = b[nt >> 1][(nt & 1) * 2 + 1];
                    mma16816(c[mt][nt][0], c[mt][nt][1], c[mt][nt][2], c[mt][nt][3],
                             a[mt][0], a[mt][1], a[mt][2], a[mt][3], b0, b1);
                }
        }
        __syncthreads();
        if (kc + 2 < 8) load_stage(kc + 2, s);
    }

    // ---- epilogue: transpose via smem, write agg as [col][node] coalesced ----
    float* trans = (float*)smg;              // generic pointer, same bytes as `smem`
    const int ocol = tid >> 2;               // 0..127
    const int oseg = tid & 3;                // 0..3 (32 floats each)
    #pragma unroll
    for (int pass = 0; pass < 2; pass++) {
        if (half == pass) {
            #pragma unroll
            for (int mt = 0; mt < 4; mt++) {
                int m = m_off + mt * 16 + (lane >> 2);
                #pragma unroll
                for (int nt = 0; nt < 4; nt++) {
                    int col = n_off + nt * 8 + (lane & 3) * 2;
                    trans[(col)     * TRS + m]     = c[mt][nt][0];
                    trans[(col + 1) * TRS + m]     = c[mt][nt][1];
                    trans[(col)     * TRS + m + 8] = c[mt][nt][2];
                    trans[(col + 1) * TRS + m + 8] = c[mt][nt][3];
                }
            }
        }
        __syncthreads();
        {
            float* C = pass ? g_agg2 : g_agg1;
            const float* src = trans + ocol * TRS + oseg * 32;
            float* dst = C + (size_t)(ntile * 128 + ocol) * Nn + mtile * 128 + oseg * 32;
            #pragma unroll
            for (int q = 0; q < 8; q++)
                ((float4*)dst)[q] = ((const float4*)src)[q];
        }
        __syncthreads();
    }
}

// ---------------- gates: GRU update + step output (coalesced) ----------------
__global__ void __launch_bounds__(256, 2) gates_kernel(
    const float* __restrict__ W3w, const float* __restrict__ W3u,
    const float* __restrict__ W4w, const float* __restrict__ W4u,
    const float* __restrict__ W5w, const float* __restrict__ W5u,
    const float* __restrict__ Wout, const float* __restrict__ bout,
    float* __restrict__ out_t)
{
    __shared__ float sWz[Hh][60], sWr[Hh][60], sWh[Hh][60];
    __shared__ float sWo[Hh][40], sB[Hh];
    const int tid = threadIdx.x;
    for (int i = tid; i < Hh * 2 * Hh; i += 256) {
        int h = i / 40, j = i % 40;
        sWz[h][j] = W3w[i]; sWr[h][j] = W4w[i]; sWh[h][j] = W5w[i];
        sWo[h][j] = Wout[i];
    }
    for (int i = tid; i < Hh * Hh; i += 256) {
        int h = i / Hh, j = i % Hh;
        sWz[h][40 + j] = W3u[i]; sWr[h][40 + j] = W4u[i]; sWh[h][40 + j] = W5u[i];
    }
    if (tid < Hh) sB[tid] = bout[tid];
    __syncthreads();

    const int b = blockIdx.x;
    const int n = blockIdx.y * 256 + tid;
    const size_t cb = (size_t)b * Hh * Nn + n;   // [col][node] base for this row

    // data vector: packed pairs of [agg_in(20), agg_out(20), fn(20)] — coalesced
    u64 d2[30];
    float fn[Hh];
    #pragma unroll
    for (int j = 0; j < 10; j++) {
        float a0 = g_agg1[cb + (size_t)(2 * j) * Nn];
        float a1 = g_agg1[cb + (size_t)(2 * j + 1) * Nn];
        d2[j] = pack2(a0, a1);
    }
    #pragma unroll
    for (int j = 0; j < 10; j++) {
        float a0 = g_agg2[cb + (size_t)(2 * j) * Nn];
        float a1 = g_agg2[cb + (size_t)(2 * j + 1) * Nn];
        d2[10 + j] = pack2(a0, a1);
    }
    #pragma unroll
    for (int h = 0; h < Hh; h++) fn[h] = g_Sf[cb + (size_t)h * Nn];
    #pragma unroll
    for (int j = 0; j < 10; j++) d2[20 + j] = pack2(fn[2 * j], fn[2 * j + 1]);

    // z and r gates
    float zv[Hh];
    {
        float rv[Hh];
        #pragma unroll
        for (int h = 0; h < Hh; h++) {
            u64 az = pack2(0.f, 0.f), ar = az;
            const float4* wz = (const float4*)&sWz[h][0];
            const float4* wr = (const float4*)&sWr[h][0];
            #pragma unroll
            for (int q = 0; q < 15; q++) {
                float4 a = wz[q], cc = wr[q];
                az = fma2(pack2(a.x, a.y), d2[2 * q], az);
                az = fma2(pack2(a.z, a.w), d2[2 * q + 1], az);
                ar = fma2(pack2(cc.x, cc.y), d2[2 * q], ar);
                ar = fma2(pack2(cc.z, cc.w), d2[2 * q + 1], ar);
            }
            zv[h] = sigmoid_fast(fsum2(az));
            rv[h] = sigmoid_fast(fsum2(ar));
        }
        #pragma unroll
        for (int j = 0; j < 10; j++)
            d2[20 + j] = pack2(rv[2 * j] * fn[2 * j], rv[2 * j + 1] * fn[2 * j + 1]);
    }

    // candidate + state update
    float fnew[Hh];
    #pragma unroll
    for (int h = 0; h < Hh; h++) {
        u64 ah = pack2(0.f, 0.f);
        const float4* wh = (const float4*)&sWh[h][0];
        #pragma unroll
        for (int q = 0; q < 15; q++) {
            float4 a = wh[q];
            ah = fma2(pack2(a.x, a.y), d2[2 * q], ah);
            ah = fma2(pack2(a.z, a.w), d2[2 * q + 1], ah);
        }
        float hv = tanh_fast(fsum2(ah));
        fnew[h] = (1.f - zv[h]) * fn[h] + zv[h] * hv;
    }

    // write back state (fp32 + fp16) — coalesced
    #pragma unroll
    for (int h = 0; h < Hh; h++) {
        size_t o = cb + (size_t)h * Nn;
        g_Sf[o] = fnew[h];
        g_Sh[o] = __float2half(fnew[h]);
    }

    // step output: [fnew, x] @ Wout^T + b  (x read coalesced from transposed copy)
    u64 e2[20];
    #pragma unroll
    for (int j = 0; j < 10; j++) e2[j] = pack2(fnew[2 * j], fnew[2 * j + 1]);
    #pragma unroll
    for (int j = 0; j < 10; j++) {
        float x0 = g_Xtf[cb + (size_t)(2 * j) * Nn];
        float x1 = g_Xtf[cb + (size_t)(2 * j + 1) * Nn];
        e2[10 + j] = pack2(x0, x1);
    }
    float o[Hh];
    #pragma unroll
    for (int h = 0; h < Hh; h++) {
        u64 acc = pack2(sB[h], 0.f);
        const float4* w = (const float4*)&sWo[h][0];
        #pragma unroll
        for (int q = 0; q < 10; q++) {
            float4 a = w[q];
            acc = fma2(pack2(a.x, a.y), e2[2 * q], acc);
            acc = fma2(pack2(a.z, a.w), e2[2 * q + 1], acc);
        }
        o[h] = fsum2(acc);
    }
    float4* op = (float4*)(out_t + ((size_t)b * Nn + n) * Hh);
    #pragma unroll
    for (int j = 0; j < 5; j++)
        op[j] = make_float4(o[4 * j], o[4 * j + 1], o[4 * j + 2], o[4 * j + 3]);
}

// ---------------- host ----------------
extern "C" void kernel_launch(void* const* d_in, const int* in_sizes, int n_in,
                              void* d_out, int out_size) {
    (void)in_sizes; (void)n_in; (void)out_size;
    const float* x    = (const float*)d_in[0];
    const float* A    = (const float*)d_in[1];
    const float* W3w  = (const float*)d_in[2];
    const float* W3u  = (const float*)d_in[3];
    const float* W4w  = (const float*)d_in[4];
    const float* W4u  = (const float*)d_in[5];
    const float* W5w  = (const float*)d_in[6];
    const float* W5u  = (const float*)d_in[7];
    const float* Wout = (const float*)d_in[8];
    const float* bo   = (const float*)d_in[9];
    float* out = (float*)d_out;

    const int gemm_smem = 2 * STAGE_B + 128;
    cudaFuncSetAttribute(gemm_kernel, cudaFuncAttributeMaxDynamicSharedMemorySize, gemm_smem);

    conv_A_kernel<<<dim3(16, 16), dim3(32, 32)>>>(A);
    conv_X_kernel<<<Bb, Nn>>>(x);

    const size_t slab = (size_t)Bb * Nn * Hh;
    for (int t = 0; t < Tt; t++) {
        gemm_kernel<<<dim3(BH / 128, Nn / 128), 512, gemm_smem>>>();
        gates_kernel<<<dim3(Bb, 2), 256>>>(W3w, W3u, W4w, W4u, W5w, W5u,
                                           Wout, bo, out + (size_t)t * slab);
    }
}